// round 1
// baseline (speedup 1.0000x reference)
#include <cuda_runtime.h>
#include <math.h>
#include <stdint.h>

#define EPSF 1e-6f
#define NINPUT 64
#define NLAYER 63

// Persistent scratch (no allocations allowed): Sinkhorn result + per-layer constants.
__device__ __align__(16) float g_P[64 * 64];        // P[k][j], row-major
__device__ __align__(16) float g_lc[NLAYER * 8];    // {bw0,bw1,A,C,e0,e1,off,nanfb} per layer

// ---------------------------------------------------------------------------
// Setup kernel: log-space Sinkhorn (20 iters) on 64x64 + per-layer F constants.
// One block, 1024 threads (32 warps). Warp w handles rows/cols {w, w+32}.
// ---------------------------------------------------------------------------
__global__ __launch_bounds__(1024) void setup_kernel(const float* __restrict__ logits,
                                                     const float* __restrict__ weights,
                                                     const float* __restrict__ biases)
{
    __shared__ float L[64][65];   // pad=65 -> conflict-free column access
    const int tid  = threadIdx.x;
    const int w    = tid >> 5;
    const int lane = tid & 31;

    for (int i = tid; i < 4096; i += 1024) L[i >> 6][i & 63] = logits[i];
    __syncthreads();

    for (int it = 0; it < 20; ++it) {
        // rows (axis=1 logsumexp)
        #pragma unroll
        for (int rr = 0; rr < 2; ++rr) {
            int r = w + rr * 32;
            float v0 = L[r][lane], v1 = L[r][lane + 32];
            float m = fmaxf(v0, v1);
            #pragma unroll
            for (int o = 16; o; o >>= 1) m = fmaxf(m, __shfl_xor_sync(0xffffffffu, m, o));
            float s = expf(v0 - m) + expf(v1 - m);
            #pragma unroll
            for (int o = 16; o; o >>= 1) s += __shfl_xor_sync(0xffffffffu, s, o);
            float lse = m + logf(s);
            L[r][lane]      = v0 - lse;
            L[r][lane + 32] = v1 - lse;
        }
        __syncthreads();
        // cols (axis=0 logsumexp)
        #pragma unroll
        for (int cc = 0; cc < 2; ++cc) {
            int c = w + cc * 32;
            float v0 = L[lane][c], v1 = L[lane + 32][c];
            float m = fmaxf(v0, v1);
            #pragma unroll
            for (int o = 16; o; o >>= 1) m = fmaxf(m, __shfl_xor_sync(0xffffffffu, m, o));
            float s = expf(v0 - m) + expf(v1 - m);
            #pragma unroll
            for (int o = 16; o; o >>= 1) s += __shfl_xor_sync(0xffffffffu, s, o);
            float lse = m + logf(s);
            L[lane][c]      = v0 - lse;
            L[lane + 32][c] = v1 - lse;
        }
        __syncthreads();
    }

    for (int i = tid; i < 4096; i += 1024) g_P[i] = expf(L[i >> 6][i & 63]);

    // Per-layer constants: F(x,y,a,w0,w1) collapsed to
    //   r = A + bw0*xc + bw1*yc + C * exp2(e0*log2(xs) + e1*log2(ys)),  xs = |off - xc|
    if (tid < NLAYER) {
        float w0 = weights[tid], w1 = 1.0f - w0, a = biases[tid];
        float A, C, cl, e0 = 0.0f, e1 = 0.0f, off;
        if (fabsf(a - 0.5f) < EPSF) {
            A = 0.0f; cl = 1.0f; C = 0.0f; off = 0.0f;            // pure linear
        } else if (a < 0.5f) {
            // De Morgan reflection: lo = 1 - F_base(1-x, 1-y, 1-a)
            float ar = fminf(fmaxf(1.0f - a, -1.0f + EPSF), 2.0f - EPSF);
            float p  = sqrtf(3.0f / fmaxf(2.0f - ar, EPSF)) - 1.0f;
            e0 = 2.0f * w0 * p; e1 = 2.0f * w1 * p;
            float bl, bg;
            if      (fabsf(ar - 2.0f) < EPSF) { bl = 0.0f; bg = 0.0f; }  // unreachable for a in [0,1)
            else if (ar >= 0.75f)             { bl = 0.0f; bg = 1.0f; }
            else if (ar > 0.5f)               { bl = 3.0f - 4.0f * ar; bg = 4.0f * ar - 2.0f; }
            else                              { bl = 1.0f; bg = 0.0f; }
            // lin(1-x,1-y) = 1 - lin(x,y)  =>  r = (1-bl) + bl*lin - bg*g(1-x,1-y)
            A = 1.0f - bl; cl = bl; C = -bg; off = 1.0f;
        } else {
            float p = sqrtf(3.0f / fmaxf(2.0f - a, EPSF)) - 1.0f;
            e0 = 2.0f * w0 * p; e1 = 2.0f * w1 * p;
            float bl, bg;
            if      (fabsf(a - 2.0f) < EPSF) { bl = 0.0f; bg = 0.0f; }   // unreachable (a < 1)
            else if (a >= 0.75f)             { bl = 0.0f; bg = 1.0f; }
            else if (a > 0.5f)               { bl = 3.0f - 4.0f * a; bg = 4.0f * a - 2.0f; }
            else                             { bl = 1.0f; bg = 0.0f; }
            A = 0.0f; cl = bl; C = bg; off = 0.0f;
        }
        float* lc = &g_lc[tid * 8];
        lc[0] = cl * w0;  lc[1] = cl * w1;  lc[2] = A;   lc[3] = C;
        lc[4] = e0;       lc[5] = e1;       lc[6] = off; lc[7] = a;  // NaN fallback = bias
    }
}

// ---------------------------------------------------------------------------
// Main kernel: per thread, one batch element.
//   leaves[j] = sum_k x[k] * P[k][j]   (f32x2 packed FFMA, P broadcast from SMEM)
//   then 63-layer left-leaning scan (fully unrolled; constant-index unpacking).
// ---------------------------------------------------------------------------
__global__ __launch_bounds__(256) void main_kernel(const float* __restrict__ x,
                                                   float* __restrict__ out,
                                                   int batch)
{
    __shared__ __align__(16) float sP[64 * 64];
    __shared__ __align__(16) float sLC[NLAYER * 8];
    const int tid = threadIdx.x;

    #pragma unroll
    for (int i = tid; i < 1024; i += 256)
        reinterpret_cast<float4*>(sP)[i] = reinterpret_cast<const float4*>(g_P)[i];
    for (int i = tid; i < NLAYER * 8; i += 256) sLC[i] = g_lc[i];
    __syncthreads();

    const int elem = blockIdx.x * 256 + tid;
    if (elem >= batch) return;

    const float4* xr = reinterpret_cast<const float4*>(x + (size_t)elem * 64);

    unsigned long long acc[32];   // 32 packed f32x2 accumulators = 64 leaves
    #pragma unroll
    for (int j = 0; j < 32; ++j) acc[j] = 0ull;

    #pragma unroll 4
    for (int kk = 0; kk < 16; ++kk) {
        float4 xv = __ldcs(&xr[kk]);            // streaming: zero reuse of x
        float xs4[4] = {xv.x, xv.y, xv.z, xv.w};
        #pragma unroll
        for (int u = 0; u < 4; ++u) {
            const int k = kk * 4 + u;
            unsigned long long x2;
            asm("mov.b64 %0, {%1, %1};" : "=l"(x2) : "f"(xs4[u]));
            const ulonglong2* pr = reinterpret_cast<const ulonglong2*>(&sP[k * 64]);
            #pragma unroll
            for (int j = 0; j < 16; ++j) {
                ulonglong2 pv = pr[j];          // LDS.128 broadcast: 4 P values
                asm("fma.rn.f32x2 %0, %1, %2, %0;" : "+l"(acc[2 * j])     : "l"(x2), "l"(pv.x));
                asm("fma.rn.f32x2 %0, %1, %2, %0;" : "+l"(acc[2 * j + 1]) : "l"(x2), "l"(pv.y));
            }
        }
    }

    // Scan: state_0 = leaf_0; state_i = F(state_{i-1}, leaf_i, b_i, w_i, 1-w_i)
    float state = __uint_as_float((unsigned)(acc[0] & 0xffffffffull));

    #pragma unroll
    for (int i = 0; i < NLAYER; ++i) {
        const int li = i + 1;
        unsigned long long pair = acc[li >> 1];
        unsigned bits = (li & 1) ? (unsigned)(pair >> 32) : (unsigned)(pair & 0xffffffffull);
        float leaf = __uint_as_float(bits);

        const float* lc = &sLC[i * 8];
        float bw0 = lc[0], bw1 = lc[1], A = lc[2], C = lc[3];
        float e0  = lc[4], e1  = lc[5], off = lc[6], nfb = lc[7];

        float xc = fminf(fmaxf(state, EPSF), 1.0f - EPSF);
        float yc = fminf(fmaxf(leaf,  EPSF), 1.0f - EPSF);
        float xs = fabsf(off - xc);             // off=0 -> xc ; off=1 -> 1-xc
        float ys = fabsf(off - yc);
        float t  = fmaf(e0, __log2f(xs), e1 * __log2f(ys));
        float g  = exp2f(t);
        float r  = fmaf(C, g, fmaf(bw1, yc, fmaf(bw0, xc, A)));
        state = isnan(r) ? nfb : r;
    }

    out[elem] = state;
}

// ---------------------------------------------------------------------------
// Launch
// ---------------------------------------------------------------------------
extern "C" void kernel_launch(void* const* d_in, const int* in_sizes, int n_in,
                              void* d_out, int out_size)
{
    const float* x       = (const float*)d_in[0];
    const float* logits  = (const float*)d_in[1];
    const float* weights = (const float*)d_in[2];
    const float* biases  = (const float*)d_in[3];
    float* out = (float*)d_out;

    int batch = in_sizes[0] / NINPUT;

    setup_kernel<<<1, 1024>>>(logits, weights, biases);
    main_kernel<<<(batch + 255) / 256, 256>>>(x, out, batch);
}

// round 3
// speedup vs baseline: 2.4427x; 2.4427x over previous
#include <cuda_runtime.h>
#include <math.h>
#include <stdint.h>

#define EPSF 1e-6f
#define NINPUT 64
#define NLAYER 63

// ---------------------------------------------------------------------------
// Persistent scratch (no allocations allowed)
// ---------------------------------------------------------------------------
__device__ __align__(16) float    g_lc[512];          // per-layer F constants (63*8 used)
__device__ __align__(16) uint32_t g_P[64 * 72];       // tf32(P[k][n]), row stride 72

// ---------------------------------------------------------------------------
// helpers
// ---------------------------------------------------------------------------
__device__ __forceinline__ uint32_t tf32_rn(float f) {
    uint32_t u;
    asm("cvt.rna.tf32.f32 %0, %1;" : "=r"(u) : "f"(f));
    return u;
}
__device__ __forceinline__ float ex2(float t) {
    float r;
    asm("ex2.approx.ftz.f32 %0, %1;" : "=f"(r) : "f"(t));
    return r;
}
__device__ __forceinline__ float lg2(float t) {
    float r;
    asm("lg2.approx.ftz.f32 %0, %1;" : "=f"(r) : "f"(t));
    return r;
}
__device__ __forceinline__ void mma_tf32(float* d, uint32_t a0, uint32_t a1, uint32_t a2,
                                         uint32_t a3, uint32_t b0, uint32_t b1) {
    asm("mma.sync.aligned.m16n8k8.row.col.f32.tf32.tf32.f32 "
        "{%0,%1,%2,%3}, {%4,%5,%6,%7}, {%8,%9}, {%0,%1,%2,%3};"
        : "+f"(d[0]), "+f"(d[1]), "+f"(d[2]), "+f"(d[3])
        : "r"(a0), "r"(a1), "r"(a2), "r"(a3), "r"(b0), "r"(b1));
}

// ---------------------------------------------------------------------------
// Setup: Sinkhorn (no-max LSE, fast intrinsics) -> tf32 P (stride 72) + consts
// ---------------------------------------------------------------------------
__global__ __launch_bounds__(1024) void setup_kernel(const float* __restrict__ logits,
                                                     const float* __restrict__ weights,
                                                     const float* __restrict__ biases)
{
    __shared__ float L[64][65];
    const int tid = threadIdx.x, w = tid >> 5, lane = tid & 31;

    for (int i = tid; i < 4096; i += 1024) L[i >> 6][i & 63] = logits[i];
    __syncthreads();

    for (int it = 0; it < 20; ++it) {
        #pragma unroll
        for (int rr = 0; rr < 2; ++rr) {                // rows (axis=1)
            int r = w + rr * 32;
            float v0 = L[r][lane], v1 = L[r][lane + 32];
            float s = __expf(v0) + __expf(v1);
            #pragma unroll
            for (int o = 16; o; o >>= 1) s += __shfl_xor_sync(0xffffffffu, s, o);
            float lse = __logf(s);
            L[r][lane] = v0 - lse; L[r][lane + 32] = v1 - lse;
        }
        __syncthreads();
        #pragma unroll
        for (int cc = 0; cc < 2; ++cc) {                // cols (axis=0)
            int c = w + cc * 32;
            float v0 = L[lane][c], v1 = L[lane + 32][c];
            float s = __expf(v0) + __expf(v1);
            #pragma unroll
            for (int o = 16; o; o >>= 1) s += __shfl_xor_sync(0xffffffffu, s, o);
            float lse = __logf(s);
            L[lane][c] = v0 - lse; L[lane + 32][c] = v1 - lse;
        }
        __syncthreads();
    }

    // P[k][n] (stride 72), tf32-rounded; pad columns left as-is (never read by mma)
    for (int i = tid; i < 4096; i += 1024) {
        int k = i >> 6, n = i & 63;
        g_P[k * 72 + n] = tf32_rn(__expf(L[k][n]));
    }
    // zero padding so the SMEM copy is deterministic
    for (int i = tid; i < 512; i += 1024) {
        int k = i >> 3, n = 64 + (i & 7);
        g_P[k * 72 + n] = 0u;
    }

    // Per-layer constants: r = A + bw0*xc + bw1*yc + C * exp2(e0*log2(xs)+e1*log2(ys))
    //   xs = |off - xc| (off=0 -> xc ; off=1 -> 1-xc)
    if (tid < NLAYER) {
        float w0 = weights[tid], w1 = 1.0f - w0, a = biases[tid];
        float A, C, cl, e0 = 0.0f, e1 = 0.0f, off;
        if (fabsf(a - 0.5f) < EPSF) {
            A = 0.0f; cl = 1.0f; C = 0.0f; off = 0.0f;
        } else if (a < 0.5f) {
            float ar = fminf(fmaxf(1.0f - a, -1.0f + EPSF), 2.0f - EPSF);
            float p  = sqrtf(3.0f / fmaxf(2.0f - ar, EPSF)) - 1.0f;
            e0 = 2.0f * w0 * p; e1 = 2.0f * w1 * p;
            float bl, bg;
            if      (fabsf(ar - 2.0f) < EPSF) { bl = 0.0f; bg = 0.0f; }
            else if (ar >= 0.75f)             { bl = 0.0f; bg = 1.0f; }
            else if (ar > 0.5f)               { bl = 3.0f - 4.0f * ar; bg = 4.0f * ar - 2.0f; }
            else                              { bl = 1.0f; bg = 0.0f; }
            A = 1.0f - bl; cl = bl; C = -bg; off = 1.0f;
        } else {
            float p = sqrtf(3.0f / fmaxf(2.0f - a, EPSF)) - 1.0f;
            e0 = 2.0f * w0 * p; e1 = 2.0f * w1 * p;
            float bl, bg;
            if      (fabsf(a - 2.0f) < EPSF) { bl = 0.0f; bg = 0.0f; }
            else if (a >= 0.75f)             { bl = 0.0f; bg = 1.0f; }
            else if (a > 0.5f)               { bl = 3.0f - 4.0f * a; bg = 4.0f * a - 2.0f; }
            else                             { bl = 1.0f; bg = 0.0f; }
            A = 0.0f; cl = bl; C = bg; off = 0.0f;
        }
        float* lc = &g_lc[tid * 8];
        lc[0] = cl * w0; lc[1] = cl * w1; lc[2] = A;   lc[3] = C;
        lc[4] = e0;      lc[5] = e1;      lc[6] = off; lc[7] = a;
    }
}

// ---------------------------------------------------------------------------
// Main: per CTA one M=128 tile via mma.sync m16n8k8 tf32, SMEM transpose, scan.
// SMEM (56KB dynamic):
//   [0,2048)       layer consts
//   [2048,20480)   P tf32  [64 k][72]   (8k+n bank-injective for B frags)
//   [20480,55296)  X tf32  [128 r][68]  (4g+tg bank-injective for A frags)
//                  ... aliased after GEMM by SL f32 [64 leaf][132] (8tg+g injective)
// ---------------------------------------------------------------------------
#define SM_LC   0
#define SM_P    2048
#define SM_X    20480
#define SM_SL   20480
#define SM_SIZE 55296
#define XS 68
#define PS 72
#define LS 132

__global__ __launch_bounds__(128) void main_kernel(const float* __restrict__ x,
                                                   float* __restrict__ out,
                                                   int batch)
{
    extern __shared__ __align__(16) uint8_t smem[];
    float*    sLC = reinterpret_cast<float*>(smem + SM_LC);
    uint32_t* sP  = reinterpret_cast<uint32_t*>(smem + SM_P);
    uint32_t* sX  = reinterpret_cast<uint32_t*>(smem + SM_X);
    float*    sSL = reinterpret_cast<float*>(smem + SM_SL);

    const int tid = threadIdx.x, wid = tid >> 5, lane = tid & 31;
    const int g = lane >> 2, tg = lane & 3;           // mma groupID / thread-in-group

    // ---- cooperative loads ----
    if (tid < 126)
        reinterpret_cast<float4*>(sLC)[tid] = reinterpret_cast<const float4*>(g_lc)[tid];
    #pragma unroll
    for (int t = 0; t < 9; ++t)                        // P: 4608 words = 1152 uint4
        reinterpret_cast<uint4*>(sP)[tid + t * 128] =
            reinterpret_cast<const uint4*>(g_P)[tid + t * 128];

    const size_t f4_limit = (size_t)batch * 16;
    const size_t f4_base  = (size_t)blockIdx.x * 2048;
    const float4* gx = reinterpret_cast<const float4*>(x);
    #pragma unroll
    for (int t = 0; t < 16; ++t) {                     // X tile: 2048 float4
        int i = tid + t * 128;
        size_t gi = f4_base + i;
        float4 v = (gi < f4_limit) ? __ldcs(&gx[gi]) : make_float4(0.f, 0.f, 0.f, 0.f);
        uint4 u;
        u.x = tf32_rn(v.x); u.y = tf32_rn(v.y); u.z = tf32_rn(v.z); u.w = tf32_rn(v.w);
        int r = i >> 4, c = (i & 15) << 2;
        *reinterpret_cast<uint4*>(&sX[r * XS + c]) = u;
    }
    __syncthreads();

    // ---- GEMM: warp wid computes rows [wid*32, wid*32+32) x 64 leaves ----
    float d[2][8][4];
    #pragma unroll
    for (int mt = 0; mt < 2; ++mt)
        #pragma unroll
        for (int nt = 0; nt < 8; ++nt)
            #pragma unroll
            for (int e = 0; e < 4; ++e) d[mt][nt][e] = 0.0f;

    const int rbase = wid * 32 + g;
    #pragma unroll
    for (int kt = 0; kt < 8; ++kt) {
        const int k0 = kt * 8 + tg;
        uint32_t b0[8], b1[8];
        #pragma unroll
        for (int nt = 0; nt < 8; ++nt) {
            int n = nt * 8 + g;
            b0[nt] = sP[k0 * PS + n];
            b1[nt] = sP[(k0 + 4) * PS + n];
        }
        #pragma unroll
        for (int mt = 0; mt < 2; ++mt) {
            int r0 = rbase + mt * 16;
            int c0 = kt * 8 + tg;
            uint32_t a0 = sX[r0 * XS + c0];
            uint32_t a1 = sX[(r0 + 8) * XS + c0];
            uint32_t a2 = sX[r0 * XS + c0 + 4];
            uint32_t a3 = sX[(r0 + 8) * XS + c0 + 4];
            #pragma unroll
            for (int nt = 0; nt < 8; ++nt)
                mma_tf32(d[mt][nt], a0, a1, a2, a3, b0[nt], b1[nt]);
        }
    }
    __syncthreads();   // all warps done reading X before SL aliases it

    // ---- epilogue: D -> SL[leaf][row] (transposed, conflict-free) ----
    #pragma unroll
    for (int mt = 0; mt < 2; ++mt) {
        int r0 = wid * 32 + mt * 16 + g;
        #pragma unroll
        for (int nt = 0; nt < 8; ++nt) {
            int c0 = nt * 8 + tg * 2;
            sSL[c0 * LS + r0]           = d[mt][nt][0];
            sSL[(c0 + 1) * LS + r0]     = d[mt][nt][1];
            sSL[c0 * LS + r0 + 8]       = d[mt][nt][2];
            sSL[(c0 + 1) * LS + r0 + 8] = d[mt][nt][3];
        }
    }
    __syncthreads();

    // ---- 63-layer scan (thread tid scans row tid) ----
    float state = sSL[tid];
    #pragma unroll
    for (int i = 0; i < NLAYER; ++i) {
        float leaf = sSL[(i + 1) * LS + tid];
        float4 c0 = *reinterpret_cast<const float4*>(&sLC[i * 8]);
        float4 c1 = *reinterpret_cast<const float4*>(&sLC[i * 8 + 4]);

        float xc = fminf(fmaxf(state, EPSF), 1.0f - EPSF);
        float yc = fminf(fmaxf(leaf,  EPSF), 1.0f - EPSF);
        float xs = fabsf(c1.z - xc);
        float ys = fabsf(c1.z - yc);
        float t  = fmaf(c1.x, lg2(xs), c1.y * lg2(ys));
        float gg = ex2(t);
        float r  = fmaf(c0.w, gg, fmaf(c0.y, yc, fmaf(c0.x, xc, c0.z)));
        state = isnan(r) ? c1.w : r;
    }

    int row = blockIdx.x * 128 + tid;
    if (row < batch) out[row] = state;
}

// ---------------------------------------------------------------------------
// Launch
// ---------------------------------------------------------------------------
extern "C" void kernel_launch(void* const* d_in, const int* in_sizes, int n_in,
                              void* d_out, int out_size)
{
    const float* x       = (const float*)d_in[0];
    const float* logits  = (const float*)d_in[1];
    const float* weights = (const float*)d_in[2];
    const float* biases  = (const float*)d_in[3];
    float* out = (float*)d_out;

    int batch = in_sizes[0] / NINPUT;

    cudaFuncSetAttribute(main_kernel, cudaFuncAttributeMaxDynamicSharedMemorySize, SM_SIZE);

    setup_kernel<<<1, 1024>>>(logits, weights, biases);
    main_kernel<<<(batch + 127) / 128, 128, SM_SIZE>>>(x, out, batch);
}